// round 10
// baseline (speedup 1.0000x reference)
#include <cuda_runtime.h>
#include <cuda_fp16.h>
#include <cstdint>

// Problem constants (fixed by the reference)
#define NN 50000
#define EE 800000
#define IN_C 512
#define HID_C 128
#define OUT_C 256
#define NB 196          // ceil(NN / 256)

// Scratch (allocation-free rule: __device__ globals)
__device__ __align__(16) __half g_h1[(size_t)NN * HID_C];    // x @ w1^T   (fp16)
__device__ __align__(16) __half g_agg1[(size_t)NN * HID_C];  // A*h1 + b1  (fp16)
__device__ __align__(16) float  g_agg2[(size_t)NN * HID_C];  // A*relu(agg1) (fp32)
__device__ int g_count[NN];
__device__ int g_rowptr[NN + 1];
__device__ int g_cursor[NN];
__device__ int g_blksum[NB];
__device__ int g_blkoff[NB];
__device__ int g_csr_src[EE];

__device__ __forceinline__ uint32_t f2tf32(float f) {
    uint32_t r;
    asm("cvt.rna.tf32.f32 %0, %1;" : "=r"(r) : "f"(f));
    return r;
}

// ---------------------------------------------------------------------------
// TF32 tensor-core GEMM with 2-stage cp.async pipeline.
// C[m][n] = sum_k A[m][k] * W[n][k] (+ bias[n]);  W is [N,K] row-major.
// Grid: x = N-blocks (fastest -> A-tile L2 reuse), y = M-blocks.
// ---------------------------------------------------------------------------
template <int K, int NTOT, bool BIAS, bool HALF_OUT>
__global__ __launch_bounds__(256)
void gemm_tf32(const float* __restrict__ A, const float* __restrict__ W,
               const float* __restrict__ bias, void* __restrict__ Cv, int M) {
    constexpr int BM = 128, BN = 64, BK = 32, LDS = BK + 4;
    constexpr int TILES = K / BK;
    __shared__ float As[2][BM][LDS];
    __shared__ float Bs[2][BN][LDS];

    const int tid = threadIdx.x;
    const int lane = tid & 31;
    const int wid = tid >> 5;
    const int warp_m = wid >> 1;
    const int warp_n = wid & 1;
    const int bm = blockIdx.y * BM;
    const int bn = blockIdx.x * BN;
    const int a_row = tid >> 3;
    const int a_c4 = (tid & 7) * 4;

    float acc[2][4][4];
#pragma unroll
    for (int mf = 0; mf < 2; mf++)
#pragma unroll
        for (int nf = 0; nf < 4; nf++)
#pragma unroll
            for (int r = 0; r < 4; r++) acc[mf][nf][r] = 0.0f;

    auto load_stage = [&](int stage, int k0) {
#pragma unroll
        for (int i = 0; i < 4; i++) {
            int row = a_row + i * 32;
            const float* gp = A + (size_t)(bm + row) * K + k0 + a_c4;
            uint32_t sa = (uint32_t)__cvta_generic_to_shared(&As[stage][row][a_c4]);
            int sz = (bm + row < M) ? 16 : 0;
            asm volatile("cp.async.cg.shared.global [%0], [%1], 16, %2;"
                         :: "r"(sa), "l"(gp), "r"(sz));
        }
#pragma unroll
        for (int i = 0; i < 2; i++) {
            int row = a_row + i * 32;
            const float* gp = W + (size_t)(bn + row) * K + k0 + a_c4;
            uint32_t sa = (uint32_t)__cvta_generic_to_shared(&Bs[stage][row][a_c4]);
            asm volatile("cp.async.cg.shared.global [%0], [%1], 16;"
                         :: "r"(sa), "l"(gp));
        }
        asm volatile("cp.async.commit_group;");
    };

    load_stage(0, 0);

    for (int t = 0; t < TILES; t++) {
        const int buf = t & 1;
        if (t + 1 < TILES) {
            load_stage(buf ^ 1, (t + 1) * BK);
            asm volatile("cp.async.wait_group 1;");
        } else {
            asm volatile("cp.async.wait_group 0;");
        }
        __syncthreads();

#pragma unroll
        for (int ks = 0; ks < BK / 8; ks++) {
            const int kb = ks * 8;
            const int kc = kb + (lane & 3);
            uint32_t a[2][4], b[4][2];
#pragma unroll
            for (int mf = 0; mf < 2; mf++) {
                int mr = warp_m * 32 + mf * 16 + (lane >> 2);
                a[mf][0] = f2tf32(As[buf][mr][kc]);
                a[mf][1] = f2tf32(As[buf][mr + 8][kc]);
                a[mf][2] = f2tf32(As[buf][mr][kc + 4]);
                a[mf][3] = f2tf32(As[buf][mr + 8][kc + 4]);
            }
#pragma unroll
            for (int nf = 0; nf < 4; nf++) {
                int nr = warp_n * 32 + nf * 8 + (lane >> 2);
                b[nf][0] = f2tf32(Bs[buf][nr][kc]);
                b[nf][1] = f2tf32(Bs[buf][nr][kc + 4]);
            }
#pragma unroll
            for (int mf = 0; mf < 2; mf++)
#pragma unroll
                for (int nf = 0; nf < 4; nf++) {
                    asm volatile(
                        "mma.sync.aligned.m16n8k8.row.col.f32.tf32.tf32.f32 "
                        "{%0,%1,%2,%3}, {%4,%5,%6,%7}, {%8,%9}, {%0,%1,%2,%3};\n"
                        : "+f"(acc[mf][nf][0]), "+f"(acc[mf][nf][1]),
                          "+f"(acc[mf][nf][2]), "+f"(acc[mf][nf][3])
                        : "r"(a[mf][0]), "r"(a[mf][1]), "r"(a[mf][2]), "r"(a[mf][3]),
                          "r"(b[nf][0]), "r"(b[nf][1]));
                }
        }
        __syncthreads();
    }

#pragma unroll
    for (int mf = 0; mf < 2; mf++) {
#pragma unroll
        for (int nf = 0; nf < 4; nf++) {
            int gr = bm + warp_m * 32 + mf * 16 + (lane >> 2);
            int gc = bn + warp_n * 32 + nf * 8 + 2 * (lane & 3);
            float b0 = 0.f, b1 = 0.f;
            if (BIAS) { b0 = __ldg(bias + gc); b1 = __ldg(bias + gc + 1); }
            if (HALF_OUT) {
                __half* C = (__half*)Cv;
                if (gr < M)
                    *reinterpret_cast<__half2*>(C + (size_t)gr * NTOT + gc) =
                        __floats2half2_rn(acc[mf][nf][0] + b0, acc[mf][nf][1] + b1);
                if (gr + 8 < M)
                    *reinterpret_cast<__half2*>(C + (size_t)(gr + 8) * NTOT + gc) =
                        __floats2half2_rn(acc[mf][nf][2] + b0, acc[mf][nf][3] + b1);
            } else {
                float* C = (float*)Cv;
                if (gr < M)
                    *reinterpret_cast<float2*>(C + (size_t)gr * NTOT + gc) =
                        make_float2(acc[mf][nf][0] + b0, acc[mf][nf][1] + b1);
                if (gr + 8 < M)
                    *reinterpret_cast<float2*>(C + (size_t)(gr + 8) * NTOT + gc) =
                        make_float2(acc[mf][nf][2] + b0, acc[mf][nf][3] + b1);
            }
        }
    }
}

// ---------------------------------------------------------------------------
// CSR construction: histogram -> block sums -> scan -> row_ptr/cursor -> fill
// ---------------------------------------------------------------------------
__global__ void hist_dst(const int* __restrict__ dst, int* __restrict__ count, int E) {
    int i = blockIdx.x * blockDim.x + threadIdx.x;
    int stride = gridDim.x * blockDim.x;
    for (; i < E; i += stride) {
        int d = dst[i];
        if ((unsigned)d < NN) atomicAdd(count + d, 1);
    }
}

__global__ __launch_bounds__(256)
void block_sums(const int* __restrict__ count, int* __restrict__ bsum) {
    __shared__ int sh[256];
    int i = blockIdx.x * 256 + threadIdx.x;
    sh[threadIdx.x] = (i < NN) ? count[i] : 0;
    __syncthreads();
    for (int off = 128; off > 0; off >>= 1) {
        if (threadIdx.x < off) sh[threadIdx.x] += sh[threadIdx.x + off];
        __syncthreads();
    }
    if (threadIdx.x == 0) bsum[blockIdx.x] = sh[0];
}

__global__ __launch_bounds__(256)
void scan_block_sums(const int* __restrict__ bsum, int* __restrict__ boff,
                     int* __restrict__ rowptr_last) {
    __shared__ int sh[256];
    int t = threadIdx.x;
    int v = (t < NB) ? bsum[t] : 0;
    sh[t] = v;
    __syncthreads();
    for (int off = 1; off < 256; off <<= 1) {
        int add = (t >= off) ? sh[t - off] : 0;
        __syncthreads();
        sh[t] += add;
        __syncthreads();
    }
    if (t < NB) boff[t] = sh[t] - v;
    if (t == 255) *rowptr_last = sh[255];
}

__global__ __launch_bounds__(256)
void write_rowptr(const int* __restrict__ count, const int* __restrict__ boff,
                  int* __restrict__ rowptr, int* __restrict__ cursor) {
    __shared__ int sh[256];
    int i = blockIdx.x * 256 + threadIdx.x;
    int t = threadIdx.x;
    int v = (i < NN) ? count[i] : 0;
    sh[t] = v;
    __syncthreads();
    for (int off = 1; off < 256; off <<= 1) {
        int add = (t >= off) ? sh[t - off] : 0;
        __syncthreads();
        sh[t] += add;
        __syncthreads();
    }
    if (i < NN) {
        int rp = boff[blockIdx.x] + sh[t] - v;
        rowptr[i] = rp;
        cursor[i] = rp;
    }
}

__global__ void fill_csr(const int* __restrict__ ei, int* __restrict__ cursor,
                         int* __restrict__ csr_src, int E) {
    const int* __restrict__ src = ei;
    const int* __restrict__ dst = ei + E;
    int i = blockIdx.x * blockDim.x + threadIdx.x;
    int stride = gridDim.x * blockDim.x;
    for (; i < E; i += stride) {
        int d = dst[i];
        if ((unsigned)d >= NN) continue;
        int pos = atomicAdd(cursor + d, 1);
        csr_src[pos] = src[i];
    }
}

// ---------------------------------------------------------------------------
// fp16 gather, 2 edges per warp-instruction.
// Row = 128 halves = 16 uint4. Half-warp h (lane>>4) handles edge slots of
// parity h; lane covers uint4 #(lane&15) of the row (8 halves -> 8 fp32 acc).
// Cross-half shfl_down(16) reduction; lanes 0-15 write the result row.
// ---------------------------------------------------------------------------
__device__ __forceinline__ void acc_u4(float acc[8], uint4 u, bool relu) {
    const __half2* h2 = reinterpret_cast<const __half2*>(&u);
#pragma unroll
    for (int p = 0; p < 4; p++) {
        float2 f = __half22float2(h2[p]);
        if (relu) { f.x = fmaxf(f.x, 0.f); f.y = fmaxf(f.y, 0.f); }
        acc[2 * p] += f.x;
        acc[2 * p + 1] += f.y;
    }
}

template <bool RELU, bool BIAS, bool HALF_OUT>
__global__ __launch_bounds__(256)
void agg_gather_x2(const uint4* __restrict__ H, const int* __restrict__ rowptr,
                   const int* __restrict__ csr_src, const float* __restrict__ bias,
                   void* __restrict__ OUT) {
    const int warp = (blockIdx.x * blockDim.x + threadIdx.x) >> 5;
    const int lane = threadIdx.x & 31;
    if (warp >= NN) return;
    const int sub = lane & 15;     // uint4 index within the row
    const int half = lane >> 4;    // edge-slot parity

    const int start = __ldg(rowptr + warp);
    const int nedge = __ldg(rowptr + warp + 1) - start;

    float acc[8];
#pragma unroll
    for (int j = 0; j < 8; j++) acc[j] = 0.f;

    const uint4 zero = make_uint4(0, 0, 0, 0);
    // Uniform trip count; per-lane predication. 4 edges per iteration
    // (2 per half-warp), 2 independent LDG.128 in flight per lane.
    for (int base = 0; base < nedge; base += 4) {
        int o0 = base + half;
        int o1 = base + half + 2;
        bool p0 = o0 < nedge;
        bool p1 = o1 < nedge;
        int s0 = p0 ? __ldg(csr_src + start + o0) : 0;
        int s1 = p1 ? __ldg(csr_src + start + o1) : 0;
        uint4 u0 = p0 ? __ldg(H + (size_t)s0 * 16 + sub) : zero;
        uint4 u1 = p1 ? __ldg(H + (size_t)s1 * 16 + sub) : zero;
        acc_u4(acc, u0, RELU);   // zero rows contribute 0 (relu(0)=0)
        acc_u4(acc, u1, RELU);
    }

    // Combine the two half-warps
#pragma unroll
    for (int j = 0; j < 8; j++)
        acc[j] += __shfl_down_sync(0xffffffffu, acc[j], 16);

    if (half == 0) {
        if (BIAS) {
            const float4* b4 = reinterpret_cast<const float4*>(bias);
            float4 ba = __ldg(b4 + 2 * sub);
            float4 bb = __ldg(b4 + 2 * sub + 1);
            acc[0] += ba.x; acc[1] += ba.y; acc[2] += ba.z; acc[3] += ba.w;
            acc[4] += bb.x; acc[5] += bb.y; acc[6] += bb.z; acc[7] += bb.w;
        }
        if (HALF_OUT) {
            __half2 h2s[4];
#pragma unroll
            for (int p = 0; p < 4; p++)
                h2s[p] = __floats2half2_rn(acc[2 * p], acc[2 * p + 1]);
            reinterpret_cast<uint4*>(OUT)[(size_t)warp * 16 + sub] =
                *reinterpret_cast<uint4*>(h2s);
        } else {
            float4* o4 = reinterpret_cast<float4*>(OUT);
            o4[(size_t)warp * 32 + 2 * sub] =
                make_float4(acc[0], acc[1], acc[2], acc[3]);
            o4[(size_t)warp * 32 + 2 * sub + 1] =
                make_float4(acc[4], acc[5], acc[6], acc[7]);
        }
    }
}

extern "C" void kernel_launch(void* const* d_in, const int* in_sizes, int n_in,
                              void* d_out, int out_size) {
    const float* x = (const float*)d_in[0];
    const int* edge_index = (const int*)d_in[1];
    const float* w1 = (const float*)d_in[2];
    const float* b1 = (const float*)d_in[3];
    const float* w2 = (const float*)d_in[4];
    const float* b2 = (const float*)d_in[5];
    float* out = (float*)d_out;

    __half* h1;   cudaGetSymbolAddress((void**)&h1, g_h1);
    __half* agg1; cudaGetSymbolAddress((void**)&agg1, g_agg1);
    float* agg2;  cudaGetSymbolAddress((void**)&agg2, g_agg2);
    int* count;   cudaGetSymbolAddress((void**)&count, g_count);
    int* rowptr;  cudaGetSymbolAddress((void**)&rowptr, g_rowptr);
    int* cursor;  cudaGetSymbolAddress((void**)&cursor, g_cursor);
    int* bsum;    cudaGetSymbolAddress((void**)&bsum, g_blksum);
    int* boff;    cudaGetSymbolAddress((void**)&boff, g_blkoff);
    int* csr_src; cudaGetSymbolAddress((void**)&csr_src, g_csr_src);

    static cudaStream_t s2 = nullptr;
    static cudaEvent_t ev_fork = nullptr, ev_join = nullptr;
    if (s2 == nullptr) {
        cudaStreamCreateWithFlags(&s2, cudaStreamNonBlocking);
        cudaEventCreateWithFlags(&ev_fork, cudaEventDisableTiming);
        cudaEventCreateWithFlags(&ev_join, cudaEventDisableTiming);
    }

    // ---- Fork: CSR build on s2, concurrent with GEMM1 ----
    cudaEventRecord(ev_fork, 0);
    cudaStreamWaitEvent(s2, ev_fork, 0);

    cudaMemsetAsync(count, 0, NN * sizeof(int), s2);
    hist_dst<<<1024, 256, 0, s2>>>(edge_index + EE, count, EE);
    block_sums<<<NB, 256, 0, s2>>>(count, bsum);
    scan_block_sums<<<1, 256, 0, s2>>>(bsum, boff, rowptr + NN);
    write_rowptr<<<NB, 256, 0, s2>>>(count, boff, rowptr, cursor);
    fill_csr<<<1024, 256, 0, s2>>>(edge_index, cursor, csr_src, EE);
    cudaEventRecord(ev_join, s2);

    // ---- h1 = x @ w1^T  -> fp16 ----
    {
        dim3 grid(HID_C / 64, (NN + 127) / 128);
        gemm_tf32<IN_C, HID_C, false, true><<<grid, 256>>>(x, w1, nullptr, h1, NN);
    }

    // ---- Join: gathers need both h1 and the CSR ----
    cudaStreamWaitEvent(0, ev_join, 0);

    // ---- agg1[n] = fp16(b1 + sum h1[src in(n)]) ----
    agg_gather_x2<false, true, true><<<(NN * 32 + 255) / 256, 256>>>(
        (const uint4*)h1, rowptr, csr_src, b1, agg1);
    // ---- agg2[n] = fp32 sum relu(agg1[src in(n)]) ----
    agg_gather_x2<true, false, false><<<(NN * 32 + 255) / 256, 256>>>(
        (const uint4*)agg1, rowptr, csr_src, nullptr, agg2);
    // ---- out = agg2 @ w2^T + b2 ----
    {
        dim3 grid(OUT_C / 64, (NN + 127) / 128);
        gemm_tf32<HID_C, OUT_C, true, false><<<grid, 256>>>(agg2, w2, b2, out, NN);
    }
}